// round 4
// baseline (speedup 1.0000x reference)
#include <cuda_runtime.h>

#define DD 128
#define TW 64           // tile width (outputs)
#define TH 8            // tile height (outputs)
#define HW (TW + 4)     // 68
#define HH (TH + 4)     // 12
#define NT 256
#define ZCHUNK 32
#define P1N (HW * HH)   // 816 halo points
#define P2N (HW * TH)   // 544 y-conv points

__device__ double g_acc;

__global__ void k_zero() { g_acc = 0.0; }

__global__ void __launch_bounds__(NT, 2) k_ssim(const float* __restrict__ x,
                                                const float* __restrict__ y) {
    constexpr float W0 = 0.120078385f;
    constexpr float W1 = 0.233880764f;
    constexpr float W2 = 0.292081722f;
    constexpr float C1 = 1e-4f;
    constexpr float C2 = 9e-4f;

    __shared__ float2 sF[HH][HW];   // raw (x', y') with halo
    __shared__ float4 sG[TH][HW];   // y-convolved 4 fields {u, v, u2+v2, uv}
    __shared__ float sred[NT / 32];

    const int t = threadIdx.x;
    const int tx = t & 31, ty = t >> 5;           // ty in 0..7
    const int nc = blockIdx.z >> 2;
    const int z0 = (blockIdx.z & 3) * ZCHUNK;
    const int w0 = blockIdx.x * TW;
    const int h0 = blockIdx.y * TH;
    const int base = nc << 21;

    // ---- P1 geometry: up to 4 halo points per thread ----
    int p1r[4], p1c[4], p1off[4];
    bool p1ok[4];
#pragma unroll
    for (int k = 0; k < 4; ++k) {
        int i = t + k * NT;
        int r = i / HW, c = i - r * HW;
        p1r[k] = r; p1c[k] = c;
        int gh = h0 + r - 2, gw = w0 + c - 2;
        bool has = (i < P1N);
        p1ok[k] = has & ((unsigned)gh < DD) & ((unsigned)gw < DD);
        p1off[k] = base + gh * DD + gw;
    }
    const bool p1has3 = (t < P1N - 3 * NT);       // t < 48

    // ---- P2 geometry: row-pairs. 272 pairs = 4 rowpairs x 68 cols ----
    int p2rp[2], p2cc[2];
#pragma unroll
    for (int m = 0; m < 2; ++m) {
        int p = t + m * NT;
        int rp = p / HW;
        p2rp[m] = rp; p2cc[m] = p - rp * HW;
    }
    const bool p2has1 = (t < 2 * P2N / 2 - NT + 0) && (t < 16);  // t < 16

    float ring0[4][5], ring1[4][5];
#pragma unroll
    for (int f = 0; f < 4; ++f)
#pragma unroll
        for (int j = 0; j < 5; ++j) { ring0[f][j] = 0.f; ring1[f][j] = 0.f; }

    float tsum = 0.f;

    // ---- prologue prefetch (plane zin = z0-2) ----
    float pX[4], pY[4];
    {
        int zin = z0 - 2;
        bool zv = ((unsigned)zin < DD);
#pragma unroll
        for (int k = 0; k < 4; ++k) {
            pX[k] = 0.f; pY[k] = 0.f;
            if (zv && p1ok[k]) {
                int a = p1off[k] + (zin << 14);
                pX[k] = x[a]; pY[k] = y[a];
            }
        }
    }

    const float WT[5] = {W0, W1, W2, W1, W0};

#pragma unroll 1
    for (int zb = 0; zb < 8; ++zb) {
#pragma unroll
        for (int u = 0; u < 5; ++u) {
            const int zi = zb * 5 + u;
            const int zin = z0 + zi - 2;
            const bool pvalid = (zi < 36) && ((unsigned)zin < DD);
            float Pv0[4], Pv1[4];

            if (pvalid) {
                // ---- P1: commit prefetched plane ----
#pragma unroll
                for (int k = 0; k < 4; ++k) {
                    if (k < 3 || p1has3) {
                        float uu = pX[k] * 0.5f + 0.5f;
                        float vv = pY[k] * 0.5f + 0.5f;
                        if (!p1ok[k]) { uu = 0.f; vv = 0.f; }
                        sF[p1r[k]][p1c[k]] = make_float2(uu, vv);
                    }
                }
            }
            // ---- prefetch next plane (LDGs fly across the barriers) ----
            {
                int nz = zin + 1;
                bool zv = (zi + 1 < 36) && ((unsigned)nz < DD);
#pragma unroll
                for (int k = 0; k < 4; ++k) {
                    pX[k] = 0.f; pY[k] = 0.f;
                    if (zv && p1ok[k]) {
                        int a = p1off[k] + (nz << 14);
                        pX[k] = x[a]; pY[k] = y[a];
                    }
                }
            }
            if (pvalid) {
                __syncthreads();
                // ---- P2: y-conv, 2 vertically adjacent points sharing 6 rows ----
#pragma unroll
                for (int m = 0; m < 2; ++m) {
                    if (m == 0 || p2has1) {
                        const int rp = p2rp[m], cc = p2cc[m];
                        float a00 = 0.f, a01 = 0.f, a02 = 0.f, a03 = 0.f;
                        float a10 = 0.f, a11 = 0.f, a12 = 0.f, a13 = 0.f;
#pragma unroll
                        for (int j = 0; j < 6; ++j) {
                            float2 uv = sF[2 * rp + j][cc];
                            float q = uv.x * uv.x + uv.y * uv.y;
                            float p = uv.x * uv.y;
                            if (j < 5) {
                                float w = WT[j];
                                a00 += w * uv.x; a01 += w * uv.y;
                                a02 += w * q;    a03 += w * p;
                            }
                            if (j > 0) {
                                float w = WT[j - 1];
                                a10 += w * uv.x; a11 += w * uv.y;
                                a12 += w * q;    a13 += w * p;
                            }
                        }
                        sG[2 * rp + 0][cc] = make_float4(a00, a01, a02, a03);
                        sG[2 * rp + 1][cc] = make_float4(a10, a11, a12, a13);
                    }
                }
                __syncthreads();
                // ---- P3: x-conv, outputs at tile cols tx and tx+32 ----
                {
                    float4 g0 = sG[ty][tx + 0];
                    float4 g1 = sG[ty][tx + 1];
                    float4 g2 = sG[ty][tx + 2];
                    float4 g3 = sG[ty][tx + 3];
                    float4 g4 = sG[ty][tx + 4];
                    Pv0[0] = W0 * (g0.x + g4.x) + W1 * (g1.x + g3.x) + W2 * g2.x;
                    Pv0[1] = W0 * (g0.y + g4.y) + W1 * (g1.y + g3.y) + W2 * g2.y;
                    Pv0[2] = W0 * (g0.z + g4.z) + W1 * (g1.z + g3.z) + W2 * g2.z;
                    Pv0[3] = W0 * (g0.w + g4.w) + W1 * (g1.w + g3.w) + W2 * g2.w;
                }
                {
                    float4 g0 = sG[ty][tx + 32];
                    float4 g1 = sG[ty][tx + 33];
                    float4 g2 = sG[ty][tx + 34];
                    float4 g3 = sG[ty][tx + 35];
                    float4 g4 = sG[ty][tx + 36];
                    Pv1[0] = W0 * (g0.x + g4.x) + W1 * (g1.x + g3.x) + W2 * g2.x;
                    Pv1[1] = W0 * (g0.y + g4.y) + W1 * (g1.y + g3.y) + W2 * g2.y;
                    Pv1[2] = W0 * (g0.z + g4.z) + W1 * (g1.z + g3.z) + W2 * g2.z;
                    Pv1[3] = W0 * (g0.w + g4.w) + W1 * (g1.w + g3.w) + W2 * g2.w;
                }
            } else {
#pragma unroll
                for (int f = 0; f < 4; ++f) { Pv0[f] = 0.f; Pv1[f] = 0.f; }
            }
            // ---- ring write at static rotation slot u ----
#pragma unroll
            for (int f = 0; f < 4; ++f) {
                ring0[f][u] = Pv0[f];
                ring1[f][u] = Pv1[f];
            }
            // ---- z-conv + SSIM for output depth z0+zi-4 ----
            if (zi >= 4 && zi < 36) {
#pragma unroll
                for (int s = 0; s < 2; ++s) {
                    float v[4];
#pragma unroll
                    for (int f = 0; f < 4; ++f) {
                        float r0 = (s == 0) ? ring0[f][(u + 1) % 5] : ring1[f][(u + 1) % 5];
                        float r1 = (s == 0) ? ring0[f][(u + 2) % 5] : ring1[f][(u + 2) % 5];
                        float r2 = (s == 0) ? ring0[f][(u + 3) % 5] : ring1[f][(u + 3) % 5];
                        float r3 = (s == 0) ? ring0[f][(u + 4) % 5] : ring1[f][(u + 4) % 5];
                        float r4 = (s == 0) ? ring0[f][u]           : ring1[f][u];
                        v[f] = W0 * (r0 + r4) + W1 * (r1 + r3) + W2 * r2;
                    }
                    float A = v[0], B = v[1], S = v[2], P = v[3];
                    float ab = A * B;
                    float a2b2 = A * A + B * B;
                    float s12 = P - ab;
                    float ssum = S - a2b2;
                    float num = (2.f * ab + C1) * (2.f * s12 + C2);
                    float den = (a2b2 + C1) * (ssum + C2);
                    tsum += __fdividef(num, den);
                }
            }
        }
    }

    // ---- block reduction ----
#pragma unroll
    for (int off = 16; off; off >>= 1)
        tsum += __shfl_xor_sync(0xFFFFFFFFu, tsum, off);
    if ((t & 31) == 0) sred[t >> 5] = tsum;
    __syncthreads();
    if (t < NT / 32) {
        float v2 = sred[t];
#pragma unroll
        for (int off = NT / 64; off; off >>= 1)
            v2 += __shfl_xor_sync(0x000000FFu, v2, off);
        if (t == 0) atomicAdd(&g_acc, (double)v2);
    }
}

__global__ void k_final(float* out) {
    out[0] = (float)(g_acc * (1.0 / 16777216.0));
}

extern "C" void kernel_launch(void* const* d_in, const int* in_sizes, int n_in,
                              void* d_out, int out_size) {
    const float* x = (const float*)d_in[0];
    const float* y = (const float*)d_in[1];
    k_zero<<<1, 1>>>();
    dim3 grid(DD / TW, DD / TH, 8 * 4);   // (2, 16, 32) = 1024 CTAs
    dim3 blk(NT);
    k_ssim<<<grid, blk>>>(x, y);
    k_final<<<1, 1>>>((float*)d_out);
}

// round 5
// speedup vs baseline: 1.1048x; 1.1048x over previous
#include <cuda_runtime.h>

#define DD 128
#define TOX 28          // outputs per warp in x (lanes 2..29)
#define TOY 16          // output rows per tile (warp w owns rows 2w, 2w+1)
#define HYR 20          // halo rows
#define NT 256
#define ZCHUNK 32

__device__ double g_acc;

__global__ void k_zero() { g_acc = 0.0; }

#define FULLM 0xFFFFFFFFu
// x-conv of a register field via shuffles (valid at lanes 2..29)
#define XC(dst, f)                                              \
    {                                                           \
        float m2 = __shfl_up_sync(FULLM, (f), 2);               \
        float m1 = __shfl_up_sync(FULLM, (f), 1);               \
        float q1 = __shfl_down_sync(FULLM, (f), 1);             \
        float q2 = __shfl_down_sync(FULLM, (f), 2);             \
        dst = W0 * (m2 + q2) + W1 * (m1 + q1) + W2 * (f);       \
    }
// rotating z-accumulator update, U compile-time. After this, acc[(U+3)%5]
// holds the COMPLETED z-conv for output depth z0+zi-4.
#define ZUPD(acc, Pv, U)                                        \
    acc[(U + 3) % 5] += W0 * (Pv);                              \
    acc[(U + 4) % 5] += W1 * (Pv);                              \
    acc[(U) % 5]     += W2 * (Pv);                              \
    acc[(U + 1) % 5] += W1 * (Pv);                              \
    acc[(U + 2) % 5]  = W0 * (Pv);

__global__ void __launch_bounds__(NT, 2) k_ssim(const float* __restrict__ x,
                                                const float* __restrict__ y) {
    constexpr float W0 = 0.120078385f;
    constexpr float W1 = 0.233880764f;
    constexpr float W2 = 0.292081722f;
    constexpr float C1 = 1e-4f;
    constexpr float C2 = 9e-4f;

    __shared__ float4 sF[2][HYR][32];    // {u, v, u^2+v^2, u*v}, double-buffered
    __shared__ float sred[NT / 32];

    const int t = threadIdx.x;
    const int lane = t & 31, w = t >> 5;
    const int x0 = blockIdx.x * TOX;
    const int gx = x0 + lane - 2;
    const int h0 = blockIdx.y * TOY;
    const int nc = blockIdx.z >> 2;
    const int z0 = (blockIdx.z & 3) * ZCHUNK;
    const int base = nc << 21;

    // halo rows owned by this warp: w, w+8, (w+16 if w<4)
    const int gh0 = h0 + w - 2;
    const int gh1 = h0 + w + 6;
    const int gh2 = h0 + w + 14;
    const bool okx = ((unsigned)gx < DD);
    const bool ok0 = okx && ((unsigned)gh0 < DD);
    const bool ok1 = okx && ((unsigned)gh1 < DD);
    const bool ok2 = okx && ((unsigned)gh2 < DD) && (w < 4);
    const int off0 = base + gh0 * DD + gx;
    const int off1 = base + gh1 * DD + gx;
    const int off2 = base + gh2 * DD + gx;
    const bool outok = (lane >= 2) && (lane <= 29) && okx;

    // z-accumulators: 2 rows x 4 fields x 5 slots
    float aA0[5], aA1[5], aA2[5], aA3[5];
    float aB0[5], aB1[5], aB2[5], aB3[5];
#pragma unroll
    for (int j = 0; j < 5; ++j) {
        aA0[j] = aA1[j] = aA2[j] = aA3[j] = 0.f;
        aB0[j] = aB1[j] = aB2[j] = aB3[j] = 0.f;
    }

    float tsum = 0.f;

    // prologue prefetch: plane zi=0 -> zin = z0-2
    float px0 = 0.f, py0 = 0.f, px1 = 0.f, py1 = 0.f, px2 = 0.f, py2 = 0.f;
    {
        int zin = z0 - 2;
        if ((unsigned)zin < DD) {
            int zo = zin << 14;
            if (ok0) { px0 = x[off0 + zo]; py0 = y[off0 + zo]; }
            if (ok1) { px1 = x[off1 + zo]; py1 = y[off1 + zo]; }
            if (ok2) { px2 = x[off2 + zo]; py2 = y[off2 + zo]; }
        }
    }

#pragma unroll 1
    for (int zb = 0; zb < 8; ++zb) {
#pragma unroll
        for (int uu = 0; uu < 5; ++uu) {
            const int zi = zb * 5 + uu;
            if (zi < 36) {
                const int zin = z0 + zi - 2;
                const bool live = ((unsigned)zin < DD);
                const int b = zi & 1;
                if (live) {
                    // commit prefetched plane
                    {
                        float u = ok0 ? px0 * 0.5f + 0.5f : 0.f;
                        float v = ok0 ? py0 * 0.5f + 0.5f : 0.f;
                        sF[b][w][lane] = make_float4(u, v, u * u + v * v, u * v);
                    }
                    {
                        float u = ok1 ? px1 * 0.5f + 0.5f : 0.f;
                        float v = ok1 ? py1 * 0.5f + 0.5f : 0.f;
                        sF[b][w + 8][lane] = make_float4(u, v, u * u + v * v, u * v);
                    }
                    if (w < 4) {
                        float u = ok2 ? px2 * 0.5f + 0.5f : 0.f;
                        float v = ok2 ? py2 * 0.5f + 0.5f : 0.f;
                        sF[b][w + 16][lane] = make_float4(u, v, u * u + v * v, u * v);
                    }
                }
                // prefetch next plane (flies across barrier + compute)
                {
                    int nz = zin + 1;
                    bool ln = ((unsigned)nz < DD) && (zi + 1 < 36);
                    int zo = nz << 14;
                    px0 = (ln && ok0) ? x[off0 + zo] : 0.f;
                    py0 = (ln && ok0) ? y[off0 + zo] : 0.f;
                    px1 = (ln && ok1) ? x[off1 + zo] : 0.f;
                    py1 = (ln && ok1) ? y[off1 + zo] : 0.f;
                    px2 = (ln && ok2) ? x[off2 + zo] : 0.f;
                    py2 = (ln && ok2) ? y[off2 + zo] : 0.f;
                }
                float PA0 = 0.f, PA1 = 0.f, PA2 = 0.f, PA3 = 0.f;
                float PB0 = 0.f, PB1 = 0.f, PB2 = 0.f, PB3 = 0.f;
                if (live) {
                    __syncthreads();
                    // y-conv: output rows 2w, 2w+1 share 6 tap rows
                    const int r = 2 * w;
                    float4 t0 = sF[b][r + 0][lane];
                    float4 t1 = sF[b][r + 1][lane];
                    float4 t2 = sF[b][r + 2][lane];
                    float4 t3 = sF[b][r + 3][lane];
                    float4 t4 = sF[b][r + 4][lane];
                    float4 t5 = sF[b][r + 5][lane];
                    float Ay0 = W0 * (t0.x + t4.x) + W1 * (t1.x + t3.x) + W2 * t2.x;
                    float Ay1 = W0 * (t0.y + t4.y) + W1 * (t1.y + t3.y) + W2 * t2.y;
                    float Ay2 = W0 * (t0.z + t4.z) + W1 * (t1.z + t3.z) + W2 * t2.z;
                    float Ay3 = W0 * (t0.w + t4.w) + W1 * (t1.w + t3.w) + W2 * t2.w;
                    float By0 = W0 * (t1.x + t5.x) + W1 * (t2.x + t4.x) + W2 * t3.x;
                    float By1 = W0 * (t1.y + t5.y) + W1 * (t2.y + t4.y) + W2 * t3.y;
                    float By2 = W0 * (t1.z + t5.z) + W1 * (t2.z + t4.z) + W2 * t3.z;
                    float By3 = W0 * (t1.w + t5.w) + W1 * (t2.w + t4.w) + W2 * t3.w;
                    // x-conv via shuffles
                    XC(PA0, Ay0); XC(PA1, Ay1); XC(PA2, Ay2); XC(PA3, Ay3);
                    XC(PB0, By0); XC(PB1, By1); XC(PB2, By2); XC(PB3, By3);
                }
                // z-accumulate (static rotation)
                ZUPD(aA0, PA0, uu); ZUPD(aA1, PA1, uu);
                ZUPD(aA2, PA2, uu); ZUPD(aA3, PA3, uu);
                ZUPD(aB0, PB0, uu); ZUPD(aB1, PB1, uu);
                ZUPD(aB2, PB2, uu); ZUPD(aB3, PB3, uu);
                // consume completed output depth z0+zi-4 at slot (uu+3)%5
                if (zi >= 4) {
                    constexpr int S0 = 0;  // placeholder for readability
                    (void)S0;
                    {
                        float A = aA0[(uu + 3) % 5], B = aA1[(uu + 3) % 5];
                        float Q = aA2[(uu + 3) % 5], P = aA3[(uu + 3) % 5];
                        float ab = A * B;
                        float a2b2 = A * A + B * B;
                        float num = (2.f * ab + C1) * (2.f * (P - ab) + C2);
                        float den = (a2b2 + C1) * ((Q - a2b2) + C2);
                        float v = __fdividef(num, den);
                        if (outok) tsum += v;
                    }
                    {
                        float A = aB0[(uu + 3) % 5], B = aB1[(uu + 3) % 5];
                        float Q = aB2[(uu + 3) % 5], P = aB3[(uu + 3) % 5];
                        float ab = A * B;
                        float a2b2 = A * A + B * B;
                        float num = (2.f * ab + C1) * (2.f * (P - ab) + C2);
                        float den = (a2b2 + C1) * ((Q - a2b2) + C2);
                        float v = __fdividef(num, den);
                        if (outok) tsum += v;
                    }
                }
            }
        }
    }

    // ---- block reduction ----
#pragma unroll
    for (int off = 16; off; off >>= 1)
        tsum += __shfl_xor_sync(FULLM, tsum, off);
    if (lane == 0) sred[w] = tsum;
    __syncthreads();
    if (t < NT / 32) {
        float v2 = sred[t];
#pragma unroll
        for (int off = NT / 64; off; off >>= 1)
            v2 += __shfl_xor_sync(0x000000FFu, v2, off);
        if (t == 0) atomicAdd(&g_acc, (double)v2);
    }
}

__global__ void k_final(float* out) {
    out[0] = (float)(g_acc * (1.0 / 16777216.0));
}

extern "C" void kernel_launch(void* const* d_in, const int* in_sizes, int n_in,
                              void* d_out, int out_size) {
    const float* x = (const float*)d_in[0];
    const float* y = (const float*)d_in[1];
    k_zero<<<1, 1>>>();
    dim3 grid((DD + TOX - 1) / TOX, DD / TOY, 8 * 4);  // (5, 8, 32) = 1280 CTAs
    dim3 blk(NT);
    k_ssim<<<grid, blk>>>(x, y);
    k_final<<<1, 1>>>((float*)d_out);
}